// round 16
// baseline (speedup 1.0000x reference)
#include <cuda_runtime.h>
#include <cuda_fp16.h>
#include <cstdint>
#include <math.h>

#define T_SEQ 1024
#define C_DIM 768
#define NH    12
#define HS    64
#define C3    (3 * C_DIM)   // 2304

// Scratch (allocation-free rule: __device__ globals) — fp16 operand buffers
__device__ __half g_Qp[NH * T_SEQ * 64];     // Q [h][t][64 dim-slots]
__device__ __half g_Kp[NH * T_SEQ * 64];     // K [h][t][64 dim-slots]
__device__ __half g_Vt[NH * 64 * T_SEQ];     // V [h][dim][1024 key-slots]
__device__ __half g_y[T_SEQ * C_DIM];        // attention out, permuted fp16
__device__ __half g_xp[T_SEQ * C_DIM];       // x permuted fp16
__device__ __half g_wattn[C3 * C_DIM];       // W_attn^T permuted fp16 [2304][768]
__device__ __half g_wproj[C_DIM * C_DIM];    // W_proj^T permuted fp16 [768][768]

// ---------------------------------------------------------------------------
// helpers
// ---------------------------------------------------------------------------
__device__ __forceinline__ void mma_f16(float* c, const uint32_t* a, const uint32_t* b) {
    asm volatile(
        "mma.sync.aligned.m16n8k16.row.col.f32.f16.f16.f32 "
        "{%0,%1,%2,%3},{%4,%5,%6,%7},{%8,%9},{%0,%1,%2,%3};"
        : "+f"(c[0]), "+f"(c[1]), "+f"(c[2]), "+f"(c[3])
        : "r"(a[0]), "r"(a[1]), "r"(a[2]), "r"(a[3]), "r"(b[0]), "r"(b[1]));
}
__device__ __forceinline__ float ex2(float x) {
    float r; asm("ex2.approx.f32 %0, %1;" : "=f"(r) : "f"(x)); return r;
}
__device__ __forceinline__ uint32_t smem_u32(const void* p) {
    uint32_t a;
    asm("{ .reg .u64 t; cvta.to.shared.u64 t, %1; cvt.u32.u64 %0, t; }" : "=r"(a) : "l"(p));
    return a;
}
__device__ __forceinline__ void cp16(uint32_t s, const void* g) {
    asm volatile("cp.async.cg.shared.global [%0], [%1], 16;" :: "r"(s), "l"(g) : "memory");
}
#define CP_COMMIT() asm volatile("cp.async.commit_group;" ::: "memory")
#define CP_WAIT1()  asm volatile("cp.async.wait_group 1;" ::: "memory")
#define CP_WAIT0()  asm volatile("cp.async.wait_group 0;" ::: "memory")
#define GBAR(id)    asm volatile("bar.sync %0, 128;" :: "r"(id) : "memory")

// 16-element k-group interleave
__device__ __forceinline__ int src16(int p) {
    const int j = p >> 2, q = p & 3;
    return 2 * j + (q & 1) + 8 * (q >> 1);
}
__device__ __forceinline__ int fwd16(int u) {
    const int j = u >> 1, e = u & 1;
    return (j < 4) ? 4 * j + e : 4 * j - 14 + e;
}

extern __shared__ char sm_dyn[];

// ---------------------------------------------------------------------------
// Fused pre-pass (unchanged, passing)
// ---------------------------------------------------------------------------
#define PREP_XBLK 192
#define PREP_WA   1728   // (2304/32) * (768/32)
#define PREP_WP   576    // (768/32) * (768/32)

__global__ __launch_bounds__(256)
void prep_all(const float* __restrict__ x, const float* __restrict__ Wa,
              const float* __restrict__ Wp,
              __half* __restrict__ xp, __half* __restrict__ wa, __half* __restrict__ wp)
{
    __shared__ float tile[32][33];
    const int b = blockIdx.x;
    const int tid = threadIdx.x;

    if (b < PREP_XBLK) {
        const int base = (b * 256 + tid) * 16;
        float f[16];
        *(float4*)(f + 0)  = *(const float4*)(x + base + 0);
        *(float4*)(f + 4)  = *(const float4*)(x + base + 4);
        *(float4*)(f + 8)  = *(const float4*)(x + base + 8);
        *(float4*)(f + 12) = *(const float4*)(x + base + 12);
        __half h[16];
#pragma unroll
        for (int p = 0; p < 16; p++) h[p] = __float2half_rn(f[src16(p)]);
        *(uint4*)(xp + base)     = *(const uint4*)(h + 0);
        *(uint4*)(xp + base + 8) = *(const uint4*)(h + 8);
        return;
    }

    const float* in;
    __half* out;
    int t, N, K;
    if (b < PREP_XBLK + PREP_WA) {
        t = b - PREP_XBLK; in = Wa; out = wa; N = C3; K = C_DIM;
    } else {
        t = b - PREP_XBLK - PREP_WA; in = Wp; out = wp; N = C_DIM; K = C_DIM;
    }
    const int ntiles_n = N / 32;
    const int n0 = (t % ntiles_n) * 32;
    const int k0 = (t / ntiles_n) * 32;
    const int tx = tid & 31;
    const int ty = tid >> 5;
#pragma unroll
    for (int j = 0; j < 4; j++)
        tile[ty + 8 * j][tx] = in[(size_t)(k0 + ty + 8 * j) * N + n0 + tx];
    __syncthreads();
    const int src = (tx & ~15) | src16(tx & 15);
#pragma unroll
    for (int j = 0; j < 4; j++)
        out[(size_t)(n0 + ty + 8 * j) * K + k0 + tx] =
            __float2half_rn(tile[src][ty + 8 * j]);
}

// ---------------------------------------------------------------------------
// qkv GEMM: BM=128, BN=128, BK=128, nk=6, STG=3, one barrier per iteration
// (slot (i+2)%3 consumed at i-1). 256 threads. smem 221184 B, RS=144 halves.
// ---------------------------------------------------------------------------
__global__ __launch_bounds__(256)
void gemm_qkv(const __half* __restrict__ Ap,
              const __half* __restrict__ Bp,
              const float* __restrict__ bias,
              __half* __restrict__ Qp, __half* __restrict__ Kp, __half* __restrict__ Vt)
{
    constexpr int BM = 128, BN = 128, BK = 128, RS = 144;
    constexpr int K = C_DIM;
    constexpr int SSH = (BM + BN) * RS;          // halves per stage
    constexpr int MT = 4, NT = 4;                // 8 warps (2x4), warp tile 64x32

    __half* Sh = (__half*)sm_dyn;
    const uint32_t sbase = smem_u32(Sh);

    const int tid  = threadIdx.x;
    const int wid  = tid >> 5;
    const int lane = tid & 31;
    const int gid  = lane >> 2;
    const int tg   = lane & 3;
    const int wm   = wid >> 2;
    const int wn   = wid & 3;
    const int m0   = blockIdx.y * BM;
    const int n0   = blockIdx.x * BN;

    float acc[MT][NT][4];
#pragma unroll
    for (int i = 0; i < MT; i++)
#pragma unroll
        for (int j = 0; j < NT; j++)
#pragma unroll
            for (int v = 0; v < 4; v++) acc[i][j][v] = 0.0f;

    const int srow = tid >> 4;                   // 0..15 (+16 steps)
    const int sch  = tid & 15;                   // chunk within 128-half row

    auto issue_stage = [&](int i) {
        const int st = i % 3;
        const int kc = i * BK;
        const uint32_t ab = sbase + st * SSH * 2;
#pragma unroll
        for (int u = 0; u < 8; u++) {            // A: 128 rows x 16 chunks
            const int row = srow + u * 16;
            cp16(ab + row * (RS * 2) + sch * 16,
                 Ap + (size_t)(m0 + row) * K + kc + sch * 8);
        }
        const uint32_t bb = ab + BM * RS * 2;
#pragma unroll
        for (int u = 0; u < 8; u++) {            // B: 128 rows x 16 chunks
            const int row = srow + u * 16;
            cp16(bb + row * (RS * 2) + sch * 16,
                 Bp + (size_t)(n0 + row) * K + kc + sch * 8);
        }
        CP_COMMIT();
    };

    issue_stage(0);
    issue_stage(1);

    constexpr int nk = K / BK;   // 6
#pragma unroll
    for (int i = 0; i < nk; i++) {
        if (i + 1 < nk) CP_WAIT1(); else CP_WAIT0();
        __syncthreads();

        const __half* Aq = Sh + (i % 3) * SSH;
        const __half* Bq = Aq + BM * RS;

#pragma unroll
        for (int g = 0; g < 8; g++) {            // 8 k16 groups
            uint32_t af[MT][4], bf[NT][2];
#pragma unroll
            for (int mt = 0; mt < MT; mt++) {
                const int row = wm * 64 + mt * 16 + gid;
                uint2 lo = *(const uint2*)&Aq[row * RS + g * 16 + tg * 4];
                uint2 hi = *(const uint2*)&Aq[(row + 8) * RS + g * 16 + tg * 4];
                af[mt][0] = lo.x; af[mt][1] = hi.x;
                af[mt][2] = lo.y; af[mt][3] = hi.y;
            }
#pragma unroll
            for (int nt = 0; nt < NT; nt++) {
                const int n = wn * 32 + nt * 8 + gid;
                uint2 bv = *(const uint2*)&Bq[n * RS + g * 16 + tg * 4];
                bf[nt][0] = bv.x; bf[nt][1] = bv.y;
            }
#pragma unroll
            for (int mt = 0; mt < MT; mt++)
#pragma unroll
                for (int nt = 0; nt < NT; nt++)
                    mma_f16(acc[mt][nt], af[mt], bf[nt]);
        }

        // slot (i+2)%3 == (i-1)%3: consumed at iter i-1, safe after this barrier
        if (i + 2 < nk) issue_stage(i + 2);
    }

    // ---- scatter epilogue
    const int sec = n0 / C_DIM;                   // 0=Q, 1=K, 2=V
    const int ccb = n0 - sec * C_DIM + wn * 32;

#pragma unroll
    for (int mt = 0; mt < MT; mt++) {
        const int r0 = m0 + wm * 64 + mt * 16 + gid;
        const int r1 = r0 + 8;
#pragma unroll
        for (int nt = 0; nt < NT; nt++) {
            const int c = n0 + wn * 32 + nt * 8 + 2 * tg;
            const float b0 = bias[c], b1 = bias[c + 1];
            const int cc0 = ccb + nt * 8 + 2 * tg;
            const int h0 = cc0 >> 6, d0 = cc0 & 63;
            const float v00 = acc[mt][nt][0] + b0;
            const float v01 = acc[mt][nt][1] + b1;
            const float v10 = acc[mt][nt][2] + b0;
            const float v11 = acc[mt][nt][3] + b1;
            if (sec < 2) {
                __half* dst = (sec == 0) ? Qp : Kp;
                const int sl = (d0 & ~15) | fwd16(d0 & 15);
                *(__half2*)&dst[h0 * 65536 + r0 * 64 + sl] = __floats2half2_rn(v00, v01);
                *(__half2*)&dst[h0 * 65536 + r1 * 64 + sl] = __floats2half2_rn(v10, v11);
            } else {
                const int d1 = d0 + 1;
                const int t0 = (r0 & ~15) | fwd16(r0 & 15);
                const int t1 = (r1 & ~15) | fwd16(r1 & 15);
                Vt[h0 * 65536 + d0 * 1024 + t0] = __float2half_rn(v00);
                Vt[h0 * 65536 + d1 * 1024 + t0] = __float2half_rn(v01);
                Vt[h0 * 65536 + d0 * 1024 + t1] = __float2half_rn(v10);
                Vt[h0 * 65536 + d1 * 1024 + t1] = __float2half_rn(v11);
            }
        }
    }
}

// ---------------------------------------------------------------------------
// proj GEMM: BM=64, BN=64, BK=128, nk=6, STG=3, one barrier/iter.
// 256 threads, smem 110592 B -> 2 CTAs/SM, grid 192.
// ---------------------------------------------------------------------------
__global__ __launch_bounds__(256, 2)
void gemm_proj(const __half* __restrict__ Ap,
               const __half* __restrict__ Bp,
               const float* __restrict__ bias,
               float* __restrict__ C)
{
    constexpr int BM = 64, BN = 64, BK = 128, RS = 144;
    constexpr int K = C_DIM, N = C_DIM;
    constexpr int SSH = (BM + BN) * RS;
    constexpr int MT = 2, NT = 2;                // 8 warps (2x4), warp tile 32x16

    __half* Sh = (__half*)sm_dyn;
    const uint32_t sbase = smem_u32(Sh);

    const int tid  = threadIdx.x;
    const int wid  = tid >> 5;
    const int lane = tid & 31;
    const int gid  = lane >> 2;
    const int tg   = lane & 3;
    const int wm   = wid >> 2;
    const int wn   = wid & 3;
    const int m0   = blockIdx.y * BM;
    const int n0   = blockIdx.x * BN;

    float acc[MT][NT][4];
#pragma unroll
    for (int i = 0; i < MT; i++)
#pragma unroll
        for (int j = 0; j < NT; j++)
#pragma unroll
            for (int v = 0; v < 4; v++) acc[i][j][v] = 0.0f;

    const int srow = tid >> 4;                   // 0..15
    const int sch  = tid & 15;

    auto issue_stage = [&](int i) {
        const int st = i % 3;
        const int kc = i * BK;
        const uint32_t ab = sbase + st * SSH * 2;
#pragma unroll
        for (int u = 0; u < 4; u++) {            // A: 64 rows x 16 chunks
            const int row = srow + u * 16;
            cp16(ab + row * (RS * 2) + sch * 16,
                 Ap + (size_t)(m0 + row) * K + kc + sch * 8);
        }
        const uint32_t bb = ab + BM * RS * 2;
#pragma unroll
        for (int u = 0; u < 4; u++) {            // B: 64 rows x 16 chunks
            const int row = srow + u * 16;
            cp16(bb + row * (RS * 2) + sch * 16,
                 Bp + (size_t)(n0 + row) * K + kc + sch * 8);
        }
        CP_COMMIT();
    };

    issue_stage(0);
    issue_stage(1);

    constexpr int nk = K / BK;   // 6
#pragma unroll
    for (int i = 0; i < nk; i++) {
        if (i + 1 < nk) CP_WAIT1(); else CP_WAIT0();
        __syncthreads();

        const __half* Aq = Sh + (i % 3) * SSH;
        const __half* Bq = Aq + BM * RS;

#pragma unroll
        for (int g = 0; g < 8; g++) {
            uint32_t af[MT][4], bf[NT][2];
#pragma unroll
            for (int mt = 0; mt < MT; mt++) {
                const int row = wm * 32 + mt * 16 + gid;
                uint2 lo = *(const uint2*)&Aq[row * RS + g * 16 + tg * 4];
                uint2 hi = *(const uint2*)&Aq[(row + 8) * RS + g * 16 + tg * 4];
                af[mt][0] = lo.x; af[mt][1] = hi.x;
                af[mt][2] = lo.y; af[mt][3] = hi.y;
            }
#pragma unroll
            for (int nt = 0; nt < NT; nt++) {
                const int n = wn * 16 + nt * 8 + gid;
                uint2 bv = *(const uint2*)&Bq[n * RS + g * 16 + tg * 4];
                bf[nt][0] = bv.x; bf[nt][1] = bv.y;
            }
#pragma unroll
            for (int mt = 0; mt < MT; mt++)
#pragma unroll
                for (int nt = 0; nt < NT; nt++)
                    mma_f16(acc[mt][nt], af[mt], bf[nt]);
        }

        if (i + 2 < nk) issue_stage(i + 2);
    }

#pragma unroll
    for (int mt = 0; mt < MT; mt++) {
        const int row = m0 + wm * 32 + mt * 16 + gid;
#pragma unroll
        for (int nt = 0; nt < NT; nt++) {
            const int col = n0 + wn * 16 + nt * 8 + 2 * tg;
            const float b0 = bias[col], b1 = bias[col + 1];
            float2 r0, r1;
            r0.x = acc[mt][nt][0] + b0; r0.y = acc[mt][nt][1] + b1;
            r1.x = acc[mt][nt][2] + b0; r1.y = acc[mt][nt][3] + b1;
            *(float2*)(C + (size_t)row * N + col)       = r0;
            *(float2*)(C + (size_t)(row + 8) * N + col) = r1;
        }
    }
}

// ---------------------------------------------------------------------------
// fp16 flash attention, dual key-group (unchanged, passing).
// ---------------------------------------------------------------------------
#define KP 5120
#define SM_ATTN_TOTAL (10 * KP * 2)   // 102400 B

__global__ __launch_bounds__(256, 2)
void attn_kernel(const __half* __restrict__ Qp, const __half* __restrict__ Kp,
                 const __half* __restrict__ Vt, __half* __restrict__ yp)
{
    __half* Sh = (__half*)sm_dyn;
    const int tid  = threadIdx.x;
    const int g    = tid >> 7;        // key group 0/1
    const int ltid = tid & 127;
    const int w    = ltid >> 5;       // warp within group
    const int lane = tid & 31;
    const int gid  = lane >> 2;
    const int tg   = lane & 3;
    const int b    = blockIdx.x;
    const int qt   = 15 - (b / NH);
    const int h    = b % NH;
    const int q0   = qt * 64;
    const int rl0  = w * 16 + gid;
    const int rl1  = rl0 + 8;

    __half* Kb = Sh + g * 5 * KP;     // 2 buffers
    __half* Vb = Kb + 2 * KP;         // 2 buffers
    __half* Ps = Kb + 4 * KP;
    const uint32_t kbase = smem_u32(Kb);
    const uint32_t vbase = smem_u32(Vb);

    // ---- Q fragments in registers
    uint32_t qf[4][4];
    {
        const __half* Q0 = Qp + h * 65536 + (size_t)(q0 + rl0) * 64;
        const __half* Q1 = Qp + h * 65536 + (size_t)(q0 + rl1) * 64;
#pragma unroll
        for (int gg = 0; gg < 4; gg++) {
            uint2 lo = *(const uint2*)(Q0 + gg * 16 + tg * 4);
            uint2 hi = *(const uint2*)(Q1 + gg * 16 + tg * 4);
            qf[gg][0] = lo.x; qf[gg][1] = hi.x;
            qf[gg][2] = lo.y; qf[gg][3] = hi.y;
        }
    }

    auto issueK = [&](int kt, int bi) {
        const __half* src = Kp + h * 65536 + (size_t)(kt * 64) * 64;
        const uint32_t dstb = kbase + bi * KP * 2;
#pragma unroll
        for (int u = 0; u < 4; u++) {
            const int c = ltid + 128 * u;
            const int row = c >> 3, ch = c & 7;
            cp16(dstb + row * 160 + ch * 16, src + row * 64 + ch * 8);
        }
        CP_COMMIT();
    };
    auto issueV = [&](int kt, int bi) {
        const uint32_t dstb = vbase + bi * KP * 2;
#pragma unroll
        for (int u = 0; u < 4; u++) {
            const int c = ltid + 128 * u;
            const int row = c >> 3, ch = c & 7;
            cp16(dstb + row * 160 + ch * 16,
                 Vt + h * 65536 + row * 1024 + kt * 64 + ch * 8);
        }
        CP_COMMIT();
    };

    float accO[8][4];
#pragma unroll
    for (int nt = 0; nt < 8; nt++)
#pragma unroll
        for (int v = 0; v < 4; v++) accO[nt][v] = 0.0f;
    float m0r = -1e30f, m1r = -1e30f, l0 = 0.0f, l1 = 0.0f;
    const float SC = 0.125f * 1.4426950408889634f;

    if (g <= qt) { issueK(g, 0); issueV(g, 0); }

    int bi = 0;
    for (int kt = g; kt <= qt; kt += 2) {
        CP_WAIT1();                   // K(kt) done
        GBAR(g + 1);

        // ---- S = Q K^T
        float accS[8][4];
#pragma unroll
        for (int nt = 0; nt < 8; nt++)
#pragma unroll
            for (int v = 0; v < 4; v++) accS[nt][v] = 0.0f;

        const __half* Kq = Kb + bi * KP;
#pragma unroll
        for (int gg = 0; gg < 4; gg++) {
#pragma unroll
            for (int nt = 0; nt < 8; nt++) {
                uint2 bv = *(const uint2*)&Kq[(nt * 8 + gid) * 80 + gg * 16 + tg * 4];
                uint32_t bf[2] = {bv.x, bv.y};
                mma_f16(accS[nt], qf[gg], bf);
            }
        }

        if (kt + 2 <= qt) issueK(kt + 2, bi ^ 1);

        // ---- mask + scale (log2 domain)
        const bool diag = (kt == qt);
#pragma unroll
        for (int nt = 0; nt < 8; nt++) {
            const int c0 = nt * 8 + 2 * tg;
#pragma unroll
            for (int v = 0; v < 4; v++) accS[nt][v] *= SC;
            if (diag) {
                if (c0     > rl0) accS[nt][0] = -1e30f;
                if (c0 + 1 > rl0) accS[nt][1] = -1e30f;
                if (c0     > rl1) accS[nt][2] = -1e30f;
                if (c0 + 1 > rl1) accS[nt][3] = -1e30f;
            }
        }

        // ---- online softmax
        float mx0 = -1e30f, mx1 = -1e30f;
#pragma unroll
        for (int nt = 0; nt < 8; nt++) {
            mx0 = fmaxf(mx0, fmaxf(accS[nt][0], accS[nt][1]));
            mx1 = fmaxf(mx1, fmaxf(accS[nt][2], accS[nt][3]));
        }
        mx0 = fmaxf(mx0, __shfl_xor_sync(0xffffffffu, mx0, 1));
        mx0 = fmaxf(mx0, __shfl_xor_sync(0xffffffffu, mx0, 2));
        mx1 = fmaxf(mx1, __shfl_xor_sync(0xffffffffu, mx1, 1));
        mx1 = fmaxf(mx1, __shfl_xor_sync(0xffffffffu, mx1, 2));
        const float mn0 = fmaxf(m0r, mx0);
        const float mn1 = fmaxf(m1r, mx1);
        const float cr0 = ex2(m0r - mn0);
        const float cr1 = ex2(m1r - mn1);
        m0r = mn0; m1r = mn1;

        float ps0 = 0.0f, ps1 = 0.0f;
#pragma unroll
        for (int nt = 0; nt < 8; nt++) {
            accS[nt][0] = ex2(accS[nt][0] - mn0);
            accS[nt][1] = ex2(accS[nt][1] - mn0);
            accS[nt][2] = ex2(accS[nt][2] - mn1);
            accS[nt][3] = ex2(accS[nt][3] - mn1);
            ps0 += accS[nt][0] + accS[nt][1];
            ps1 += accS[nt][2] + accS[nt][3];
        }
        ps0 += __shfl_xor_sync(0xffffffffu, ps0, 1);
        ps0 += __shfl_xor_sync(0xffffffffu, ps0, 2);
        ps1 += __shfl_xor_sync(0xffffffffu, ps1, 1);
        ps1 += __shfl_xor_sync(0xffffffffu, ps1, 2);
        l0 = l0 * cr0 + ps0;
        l1 = l1 * cr1 + ps1;
#pragma unroll
        for (int nt = 0; nt < 8; nt++) {
            accO[nt][0] *= cr0; accO[nt][1] *= cr0;
            accO[nt][2] *= cr1; accO[nt][3] *= cr1;
        }

        // ---- wait V(kt), then P store + PV
        if (kt + 2 <= qt) CP_WAIT1(); else CP_WAIT0();
        GBAR(g + 1);

        __syncwarp();
#pragma unroll
        for (int nt = 0; nt < 8; nt++) {
            const int c0 = nt * 8 + 2 * tg;
            const int sl = (c0 >> 4) * 16 + 4 * tg + 2 * (nt & 1);
            *(__half2*)&Ps[rl0 * 80 + sl] = __floats2half2_rn(accS[nt][0], accS[nt][1]);
            *(__half2*)&Ps[rl1 * 80 + sl] = __floats2half2_rn(accS[nt][2], accS[nt][3]);
        }
        __syncwarp();

        const __half* Vq = Vb + bi * KP;
#pragma unroll
        for (int gg = 0; gg < 4; gg++) {
            uint32_t af[4];
            uint2 lo = *(const uint2*)&Ps[rl0 * 80 + gg * 16 + tg * 4];
            uint2 hi = *(const uint2*)&Ps[rl1 * 80 + gg * 16 + tg * 4];
            af[0] = lo.x; af[1] = hi.x; af[2] = lo.y; af[3] = hi.y;
#pragma unroll
            for (int nt = 0; nt < 8; nt++) {
                uint2 bv = *(const uint2*)&Vq[(nt * 8 + gid) * 80 + gg * 16 + tg * 4];
                uint32_t bf[2] = {bv.x, bv.y};
                mma_f16(accO[nt], af, bf);
            }
        }

        if (kt + 2 <= qt) issueV(kt + 2, bi ^ 1);
        bi ^= 1;
    }

    // ---- merge the two groups' partial softmax states
    __syncthreads();                   // both groups done computing
    float* MB = (float*)(Sh + 5 * KP); // group 1 region (free now)
    float* OB = MB + 512;
    if (g == 1) {
        const int s = ltid;
        MB[s * 4 + 0] = m0r; MB[s * 4 + 1] = m1r;
        MB[s * 4 + 2] = l0;  MB[s * 4 + 3] = l1;
#pragma unroll
        for (int nt = 0; nt < 8; nt++)
#pragma unroll
            for (int v = 0; v < 4; v++)
                OB[s * 32 + nt * 4 + v] = accO[nt][v];
    }
    __syncthreads();
    if (g == 0) {
        const int s = ltid;
        const float mb0 = MB[s * 4 + 0], mb1 = MB[s * 4 + 1];
        const float lb0 = MB[s * 4 + 2], lb1 = MB[s * 4 + 3];
        const float mm0 = fmaxf(m0r, mb0), mm1 = fmaxf(m1r, mb1);
        const float ca0 = ex2(m0r - mm0), cb0 = ex2(mb0 - mm0);
        const float ca1 = ex2(m1r - mm1), cb1 = ex2(mb1 - mm1);
        const float inv0 = 1.0f / (l0 * ca0 + lb0 * cb0);
        const float inv1 = 1.0f / (l1 * ca1 + lb1 * cb1);
        const int gr0 = q0 + rl0;
        const int gr1 = q0 + rl1;
#pragma unroll
        for (int nt = 0; nt < 8; nt++) {
            const float o0 = accO[nt][0] * ca0 + OB[s * 32 + nt * 4 + 0] * cb0;
            const float o1 = accO[nt][1] * ca0 + OB[s * 32 + nt * 4 + 1] * cb0;
            const float o2 = accO[nt][2] * ca1 + OB[s * 32 + nt * 4 + 2] * cb1;
            const float o3 = accO[nt][3] * ca1 + OB[s * 32 + nt * 4 + 3] * cb1;
            const int c0 = nt * 8 + 2 * tg;
            const int sl = (c0 >> 4) * 16 + 4 * tg + 2 * (nt & 1);
            const int cb = h * 64 + sl;
            *(__half2*)&yp[(size_t)gr0 * C_DIM + cb] =
                __floats2half2_rn(o0 * inv0, o1 * inv0);
            *(__half2*)&yp[(size_t)gr1 * C_DIM + cb] =
                __floats2half2_rn(o2 * inv1, o3 * inv1);
        }
    }
}

// ---------------------------------------------------------------------------
extern "C" void kernel_launch(void* const* d_in, const int* in_sizes, int n_in,
                              void* d_out, int out_size)
{
    const float* x      = (const float*)d_in[0];
    const float* W_attn = (const float*)d_in[1];
    const float* b_attn = (const float*)d_in[2];
    const float* W_proj = (const float*)d_in[3];
    const float* b_proj = (const float*)d_in[4];
    float* out = (float*)d_out;

    __half *Qp, *Kp, *Vt, *y, *xp, *wa, *wp;
    cudaGetSymbolAddress((void**)&Qp, g_Qp);
    cudaGetSymbolAddress((void**)&Kp, g_Kp);
    cudaGetSymbolAddress((void**)&Vt, g_Vt);
    cudaGetSymbolAddress((void**)&y,  g_y);
    cudaGetSymbolAddress((void**)&xp, g_xp);
    cudaGetSymbolAddress((void**)&wa, g_wattn);
    cudaGetSymbolAddress((void**)&wp, g_wproj);

    const int smem_qkv  = 3 * (128 + 128) * 144 * 2;  // 221184
    const int smem_proj = 3 * (64 + 64) * 144 * 2;    // 110592
    cudaFuncSetAttribute(gemm_qkv, cudaFuncAttributeMaxDynamicSharedMemorySize, smem_qkv);
    cudaFuncSetAttribute(gemm_proj, cudaFuncAttributeMaxDynamicSharedMemorySize, smem_proj);
    cudaFuncSetAttribute(attn_kernel, cudaFuncAttributeMaxDynamicSharedMemorySize,
                         SM_ATTN_TOTAL);

    // 0) fused pre-pass (single launch)
    prep_all<<<PREP_XBLK + PREP_WA + PREP_WP, 256>>>(x, W_attn, W_proj, xp, wa, wp);

    // 1) qkv GEMM with scatter epilogue -> Qp/Kp/Vt
    {
        dim3 grid(C3 / 128, T_SEQ / 128);   // (18, 8) = 144
        gemm_qkv<<<grid, 256, smem_qkv>>>(xp, wa, b_attn, Qp, Kp, Vt);
    }
    // 2) attention (dual key-group) -> y (permuted fp16)
    {
        attn_kernel<<<(T_SEQ / 64) * NH, 256, SM_ATTN_TOTAL>>>(Qp, Kp, Vt, y);
    }
    // 3) proj GEMM -> out (fp32)
    {
        dim3 grid(C_DIM / 64, T_SEQ / 64);  // (12, 16) = 192
        gemm_proj<<<grid, 256, smem_proj>>>(y, wp, b_proj, out);
    }
}

// round 17
// speedup vs baseline: 1.0452x; 1.0452x over previous
#include <cuda_runtime.h>
#include <cuda_fp16.h>
#include <cstdint>
#include <math.h>

#define T_SEQ 1024
#define C_DIM 768
#define NH    12
#define HS    64
#define C3    (3 * C_DIM)   // 2304

// Scratch (allocation-free rule: __device__ globals) — fp16 operand buffers
__device__ __half g_Qp[NH * T_SEQ * 64];     // Q [h][t][64 dim-slots]
__device__ __half g_Kp[NH * T_SEQ * 64];     // K [h][t][64 dim-slots]
__device__ __half g_Vt[NH * 64 * T_SEQ];     // V [h][dim][1024 key-slots]
__device__ __half g_y[T_SEQ * C_DIM];        // attention out, permuted fp16
__device__ __half g_xp[T_SEQ * C_DIM];       // x permuted fp16
__device__ __half g_wattn[C3 * C_DIM];       // W_attn^T permuted fp16 [2304][768]
__device__ __half g_wproj[C_DIM * C_DIM];    // W_proj^T permuted fp16 [768][768]

// ---------------------------------------------------------------------------
// helpers
// ---------------------------------------------------------------------------
__device__ __forceinline__ void mma_f16(float* c, const uint32_t* a, const uint32_t* b) {
    asm volatile(
        "mma.sync.aligned.m16n8k16.row.col.f32.f16.f16.f32 "
        "{%0,%1,%2,%3},{%4,%5,%6,%7},{%8,%9},{%0,%1,%2,%3};"
        : "+f"(c[0]), "+f"(c[1]), "+f"(c[2]), "+f"(c[3])
        : "r"(a[0]), "r"(a[1]), "r"(a[2]), "r"(a[3]), "r"(b[0]), "r"(b[1]));
}
__device__ __forceinline__ float ex2(float x) {
    float r; asm("ex2.approx.f32 %0, %1;" : "=f"(r) : "f"(x)); return r;
}
__device__ __forceinline__ uint32_t smem_u32(const void* p) {
    uint32_t a;
    asm("{ .reg .u64 t; cvta.to.shared.u64 t, %1; cvt.u32.u64 %0, t; }" : "=r"(a) : "l"(p));
    return a;
}
__device__ __forceinline__ void cp16(uint32_t s, const void* g) {
    asm volatile("cp.async.cg.shared.global [%0], [%1], 16;" :: "r"(s), "l"(g) : "memory");
}
#define CP_COMMIT() asm volatile("cp.async.commit_group;" ::: "memory")
#define CP_WAIT1()  asm volatile("cp.async.wait_group 1;" ::: "memory")
#define CP_WAIT0()  asm volatile("cp.async.wait_group 0;" ::: "memory")
#define GBAR(id)    asm volatile("bar.sync %0, 128;" :: "r"(id) : "memory")

// 16-element k-group interleave
__device__ __forceinline__ int src16(int p) {
    const int j = p >> 2, q = p & 3;
    return 2 * j + (q & 1) + 8 * (q >> 1);
}
__device__ __forceinline__ int fwd16(int u) {
    const int j = u >> 1, e = u & 1;
    return (j < 4) ? 4 * j + e : 4 * j - 14 + e;
}

extern __shared__ char sm_dyn[];

// ---------------------------------------------------------------------------
// Fused pre-pass (unchanged, passing)
// ---------------------------------------------------------------------------
#define PREP_XBLK 192
#define PREP_WA   1728   // (2304/32) * (768/32)
#define PREP_WP   576    // (768/32) * (768/32)

__global__ __launch_bounds__(256)
void prep_all(const float* __restrict__ x, const float* __restrict__ Wa,
              const float* __restrict__ Wp,
              __half* __restrict__ xp, __half* __restrict__ wa, __half* __restrict__ wp)
{
    __shared__ float tile[32][33];
    const int b = blockIdx.x;
    const int tid = threadIdx.x;

    if (b < PREP_XBLK) {
        const int base = (b * 256 + tid) * 16;
        float f[16];
        *(float4*)(f + 0)  = *(const float4*)(x + base + 0);
        *(float4*)(f + 4)  = *(const float4*)(x + base + 4);
        *(float4*)(f + 8)  = *(const float4*)(x + base + 8);
        *(float4*)(f + 12) = *(const float4*)(x + base + 12);
        __half h[16];
#pragma unroll
        for (int p = 0; p < 16; p++) h[p] = __float2half_rn(f[src16(p)]);
        *(uint4*)(xp + base)     = *(const uint4*)(h + 0);
        *(uint4*)(xp + base + 8) = *(const uint4*)(h + 8);
        return;
    }

    const float* in;
    __half* out;
    int t, N, K;
    if (b < PREP_XBLK + PREP_WA) {
        t = b - PREP_XBLK; in = Wa; out = wa; N = C3; K = C_DIM;
    } else {
        t = b - PREP_XBLK - PREP_WA; in = Wp; out = wp; N = C_DIM; K = C_DIM;
    }
    const int ntiles_n = N / 32;
    const int n0 = (t % ntiles_n) * 32;
    const int k0 = (t / ntiles_n) * 32;
    const int tx = tid & 31;
    const int ty = tid >> 5;
#pragma unroll
    for (int j = 0; j < 4; j++)
        tile[ty + 8 * j][tx] = in[(size_t)(k0 + ty + 8 * j) * N + n0 + tx];
    __syncthreads();
    const int src = (tx & ~15) | src16(tx & 15);
#pragma unroll
    for (int j = 0; j < 4; j++)
        out[(size_t)(n0 + ty + 8 * j) * K + k0 + tx] =
            __float2half_rn(tile[src][ty + 8 * j]);
}

// ---------------------------------------------------------------------------
// qkv GEMM (round-14 config, best): BM=128, BN=128, BK=64, STG=2,
// 256 threads, fully unrolled, two barriers/iter. smem 81920 B.
// ---------------------------------------------------------------------------
__global__ __launch_bounds__(256, 2)
void gemm_qkv(const __half* __restrict__ Ap,
              const __half* __restrict__ Bp,
              const float* __restrict__ bias,
              __half* __restrict__ Qp, __half* __restrict__ Kp, __half* __restrict__ Vt)
{
    constexpr int BM = 128, BN = 128, BK = 64, RS = 80;
    constexpr int K = C_DIM;
    constexpr int SSH = (BM + BN) * RS;
    constexpr int MT = 4, NT = 4;

    __half* Sh = (__half*)sm_dyn;
    const uint32_t sbase = smem_u32(Sh);

    const int tid  = threadIdx.x;
    const int wid  = tid >> 5;
    const int lane = tid & 31;
    const int gid  = lane >> 2;
    const int tg   = lane & 3;
    const int wm   = wid >> 2;
    const int wn   = wid & 3;
    const int m0   = blockIdx.y * BM;
    const int n0   = blockIdx.x * BN;

    float acc[MT][NT][4];
#pragma unroll
    for (int i = 0; i < MT; i++)
#pragma unroll
        for (int j = 0; j < NT; j++)
#pragma unroll
            for (int v = 0; v < 4; v++) acc[i][j][v] = 0.0f;

    const int srow = tid >> 3;
    const int sch  = tid & 7;

    auto issue_stage = [&](int i) {
        const int st = i & 1;
        const int kc = i * BK;
        const uint32_t ab = sbase + st * SSH * 2;
#pragma unroll
        for (int u = 0; u < 4; u++) {
            const int row = srow + u * 32;
            cp16(ab + row * (RS * 2) + sch * 16,
                 Ap + (size_t)(m0 + row) * K + kc + sch * 8);
        }
        const uint32_t bb = ab + BM * RS * 2;
#pragma unroll
        for (int u = 0; u < 4; u++) {
            const int row = srow + u * 32;
            cp16(bb + row * (RS * 2) + sch * 16,
                 Bp + (size_t)(n0 + row) * K + kc + sch * 8);
        }
        CP_COMMIT();
    };

    issue_stage(0);
    issue_stage(1);

    constexpr int nk = K / BK;   // 12
#pragma unroll
    for (int i = 0; i < nk; i++) {
        if (i + 1 < nk) CP_WAIT1(); else CP_WAIT0();
        __syncthreads();

        const __half* Aq = Sh + (i & 1) * SSH;
        const __half* Bq = Aq + BM * RS;

#pragma unroll
        for (int g = 0; g < 4; g++) {
            uint32_t af[MT][4], bf[NT][2];
#pragma unroll
            for (int mt = 0; mt < MT; mt++) {
                const int row = wm * 64 + mt * 16 + gid;
                uint2 lo = *(const uint2*)&Aq[row * RS + g * 16 + tg * 4];
                uint2 hi = *(const uint2*)&Aq[(row + 8) * RS + g * 16 + tg * 4];
                af[mt][0] = lo.x; af[mt][1] = hi.x;
                af[mt][2] = lo.y; af[mt][3] = hi.y;
            }
#pragma unroll
            for (int nt = 0; nt < NT; nt++) {
                const int n = wn * 32 + nt * 8 + gid;
                uint2 bv = *(const uint2*)&Bq[n * RS + g * 16 + tg * 4];
                bf[nt][0] = bv.x; bf[nt][1] = bv.y;
            }
#pragma unroll
            for (int mt = 0; mt < MT; mt++)
#pragma unroll
                for (int nt = 0; nt < NT; nt++)
                    mma_f16(acc[mt][nt], af[mt], bf[nt]);
        }

        if (i + 2 < nk) {
            __syncthreads();
            issue_stage(i + 2);
        }
    }

    // ---- scatter epilogue
    const int sec = n0 / C_DIM;
    const int ccb = n0 - sec * C_DIM + wn * 32;

#pragma unroll
    for (int mt = 0; mt < MT; mt++) {
        const int r0 = m0 + wm * 64 + mt * 16 + gid;
        const int r1 = r0 + 8;
#pragma unroll
        for (int nt = 0; nt < NT; nt++) {
            const int c = n0 + wn * 32 + nt * 8 + 2 * tg;
            const float b0 = bias[c], b1 = bias[c + 1];
            const int cc0 = ccb + nt * 8 + 2 * tg;
            const int h0 = cc0 >> 6, d0 = cc0 & 63;
            const float v00 = acc[mt][nt][0] + b0;
            const float v01 = acc[mt][nt][1] + b1;
            const float v10 = acc[mt][nt][2] + b0;
            const float v11 = acc[mt][nt][3] + b1;
            if (sec < 2) {
                __half* dst = (sec == 0) ? Qp : Kp;
                const int sl = (d0 & ~15) | fwd16(d0 & 15);
                *(__half2*)&dst[h0 * 65536 + r0 * 64 + sl] = __floats2half2_rn(v00, v01);
                *(__half2*)&dst[h0 * 65536 + r1 * 64 + sl] = __floats2half2_rn(v10, v11);
            } else {
                const int d1 = d0 + 1;
                const int t0 = (r0 & ~15) | fwd16(r0 & 15);
                const int t1 = (r1 & ~15) | fwd16(r1 & 15);
                Vt[h0 * 65536 + d0 * 1024 + t0] = __float2half_rn(v00);
                Vt[h0 * 65536 + d1 * 1024 + t0] = __float2half_rn(v01);
                Vt[h0 * 65536 + d0 * 1024 + t1] = __float2half_rn(v10);
                Vt[h0 * 65536 + d1 * 1024 + t1] = __float2half_rn(v11);
            }
        }
    }
}

// ---------------------------------------------------------------------------
// proj GEMM (round-14 config, best): BM=128, BN=64, BK=64, STG=2,
// 256 threads (MT=4, NT=2), fully unrolled. Grid (12,8)=96.
// ---------------------------------------------------------------------------
__global__ __launch_bounds__(256, 2)
void gemm_proj(const __half* __restrict__ Ap,
               const __half* __restrict__ Bp,
               const float* __restrict__ bias,
               float* __restrict__ C)
{
    constexpr int BM = 128, BN = 64, BK = 64, RS = 80;
    constexpr int K = C_DIM, N = C_DIM;
    constexpr int SSH = (BM + BN) * RS;
    constexpr int MT = 4, NT = 2;

    __half* Sh = (__half*)sm_dyn;
    const uint32_t sbase = smem_u32(Sh);

    const int tid  = threadIdx.x;
    const int wid  = tid >> 5;
    const int lane = tid & 31;
    const int gid  = lane >> 2;
    const int tg   = lane & 3;
    const int wm   = wid >> 2;
    const int wn   = wid & 3;
    const int m0   = blockIdx.y * BM;
    const int n0   = blockIdx.x * BN;

    float acc[MT][NT][4];
#pragma unroll
    for (int i = 0; i < MT; i++)
#pragma unroll
        for (int j = 0; j < NT; j++)
#pragma unroll
            for (int v = 0; v < 4; v++) acc[i][j][v] = 0.0f;

    const int srow = tid >> 3;
    const int sch  = tid & 7;

    auto issue_stage = [&](int i) {
        const int st = i & 1;
        const int kc = i * BK;
        const uint32_t ab = sbase + st * SSH * 2;
#pragma unroll
        for (int u = 0; u < 4; u++) {
            const int row = srow + u * 32;
            cp16(ab + row * (RS * 2) + sch * 16,
                 Ap + (size_t)(m0 + row) * K + kc + sch * 8);
        }
        const uint32_t bb = ab + BM * RS * 2;
#pragma unroll
        for (int u = 0; u < 2; u++) {
            const int row = srow + u * 32;
            cp16(bb + row * (RS * 2) + sch * 16,
                 Bp + (size_t)(n0 + row) * K + kc + sch * 8);
        }
        CP_COMMIT();
    };

    issue_stage(0);
    issue_stage(1);

    constexpr int nk = K / BK;   // 12
#pragma unroll
    for (int i = 0; i < nk; i++) {
        if (i + 1 < nk) CP_WAIT1(); else CP_WAIT0();
        __syncthreads();

        const __half* Aq = Sh + (i & 1) * SSH;
        const __half* Bq = Aq + BM * RS;

#pragma unroll
        for (int g = 0; g < 4; g++) {
            uint32_t af[MT][4], bf[NT][2];
#pragma unroll
            for (int mt = 0; mt < MT; mt++) {
                const int row = wm * 64 + mt * 16 + gid;
                uint2 lo = *(const uint2*)&Aq[row * RS + g * 16 + tg * 4];
                uint2 hi = *(const uint2*)&Aq[(row + 8) * RS + g * 16 + tg * 4];
                af[mt][0] = lo.x; af[mt][1] = hi.x;
                af[mt][2] = lo.y; af[mt][3] = hi.y;
            }
#pragma unroll
            for (int nt = 0; nt < NT; nt++) {
                const int n = wn * 16 + nt * 8 + gid;
                uint2 bv = *(const uint2*)&Bq[n * RS + g * 16 + tg * 4];
                bf[nt][0] = bv.x; bf[nt][1] = bv.y;
            }
#pragma unroll
            for (int mt = 0; mt < MT; mt++)
#pragma unroll
                for (int nt = 0; nt < NT; nt++)
                    mma_f16(acc[mt][nt], af[mt], bf[nt]);
        }

        if (i + 2 < nk) {
            __syncthreads();
            issue_stage(i + 2);
        }
    }

#pragma unroll
    for (int mt = 0; mt < MT; mt++) {
        const int row = m0 + wm * 64 + mt * 16 + gid;
#pragma unroll
        for (int nt = 0; nt < NT; nt++) {
            const int col = n0 + wn * 16 + nt * 8 + 2 * tg;
            const float b0 = bias[col], b1 = bias[col + 1];
            float2 r0, r1;
            r0.x = acc[mt][nt][0] + b0; r0.y = acc[mt][nt][1] + b1;
            r1.x = acc[mt][nt][2] + b0; r1.y = acc[mt][nt][3] + b1;
            *(float2*)(C + (size_t)row * N + col)       = r0;
            *(float2*)(C + (size_t)(row + 8) * N + col) = r1;
        }
    }
}

// ---------------------------------------------------------------------------
// fp16 flash attention, QUAD key-group: 512 threads = 4 groups x 4 warps.
// Group g handles key tiles kt ≡ g (mod 4), private K/V double-buffers + Ps +
// named barrier (g+1). 4-way exact online-softmax merge at the end.
// smem: 4 groups x [Kb0,Kb1,Vb0,Vb1,Ps] x 5120 halves = 204800 B, 1 CTA/SM.
// ---------------------------------------------------------------------------
#define KP 5120
#define SM_ATTN_TOTAL (20 * KP * 2)   // 204800 B

__global__ __launch_bounds__(512, 1)
void attn_kernel(const __half* __restrict__ Qp, const __half* __restrict__ Kp,
                 const __half* __restrict__ Vt, __half* __restrict__ yp)
{
    __half* Sh = (__half*)sm_dyn;
    const int tid  = threadIdx.x;
    const int g    = tid >> 7;        // key group 0..3
    const int ltid = tid & 127;
    const int w    = ltid >> 5;       // warp within group
    const int lane = tid & 31;
    const int gid  = lane >> 2;
    const int tg   = lane & 3;
    const int b    = blockIdx.x;
    const int qt   = 15 - (b / NH);
    const int h    = b % NH;
    const int q0   = qt * 64;
    const int rl0  = w * 16 + gid;
    const int rl1  = rl0 + 8;

    __half* Kb = Sh + g * 5 * KP;     // 2 buffers
    __half* Vb = Kb + 2 * KP;         // 2 buffers
    __half* Ps = Kb + 4 * KP;
    const uint32_t kbase = smem_u32(Kb);
    const uint32_t vbase = smem_u32(Vb);

    // ---- Q fragments in registers
    uint32_t qf[4][4];
    {
        const __half* Q0 = Qp + h * 65536 + (size_t)(q0 + rl0) * 64;
        const __half* Q1 = Qp + h * 65536 + (size_t)(q0 + rl1) * 64;
#pragma unroll
        for (int gg = 0; gg < 4; gg++) {
            uint2 lo = *(const uint2*)(Q0 + gg * 16 + tg * 4);
            uint2 hi = *(const uint2*)(Q1 + gg * 16 + tg * 4);
            qf[gg][0] = lo.x; qf[gg][1] = hi.x;
            qf[gg][2] = lo.y; qf[gg][3] = hi.y;
        }
    }

    auto issueK = [&](int kt, int bi) {
        const __half* src = Kp + h * 65536 + (size_t)(kt * 64) * 64;
        const uint32_t dstb = kbase + bi * KP * 2;
#pragma unroll
        for (int u = 0; u < 4; u++) {
            const int c = ltid + 128 * u;
            const int row = c >> 3, ch = c & 7;
            cp16(dstb + row * 160 + ch * 16, src + row * 64 + ch * 8);
        }
        CP_COMMIT();
    };
    auto issueV = [&](int kt, int bi) {
        const uint32_t dstb = vbase + bi * KP * 2;
#pragma unroll
        for (int u = 0; u < 4; u++) {
            const int c = ltid + 128 * u;
            const int row = c >> 3, ch = c & 7;
            cp16(dstb + row * 160 + ch * 16,
                 Vt + h * 65536 + row * 1024 + kt * 64 + ch * 8);
        }
        CP_COMMIT();
    };

    float accO[8][4];
#pragma unroll
    for (int nt = 0; nt < 8; nt++)
#pragma unroll
        for (int v = 0; v < 4; v++) accO[nt][v] = 0.0f;
    float m0r = -1e30f, m1r = -1e30f, l0 = 0.0f, l1 = 0.0f;
    const float SC = 0.125f * 1.4426950408889634f;

    if (g <= qt) { issueK(g, 0); issueV(g, 0); }

    int bi = 0;
    for (int kt = g; kt <= qt; kt += 4) {
        CP_WAIT1();                   // K(kt) done
        GBAR(g + 1);

        // ---- S = Q K^T
        float accS[8][4];
#pragma unroll
        for (int nt = 0; nt < 8; nt++)
#pragma unroll
            for (int v = 0; v < 4; v++) accS[nt][v] = 0.0f;

        const __half* Kq = Kb + bi * KP;
#pragma unroll
        for (int gg = 0; gg < 4; gg++) {
#pragma unroll
            for (int nt = 0; nt < 8; nt++) {
                uint2 bv = *(const uint2*)&Kq[(nt * 8 + gid) * 80 + gg * 16 + tg * 4];
                uint32_t bf[2] = {bv.x, bv.y};
                mma_f16(accS[nt], qf[gg], bf);
            }
        }

        if (kt + 4 <= qt) issueK(kt + 4, bi ^ 1);

        // ---- mask + scale (log2 domain)
        const bool diag = (kt == qt);
#pragma unroll
        for (int nt = 0; nt < 8; nt++) {
            const int c0 = nt * 8 + 2 * tg;
#pragma unroll
            for (int v = 0; v < 4; v++) accS[nt][v] *= SC;
            if (diag) {
                if (c0     > rl0) accS[nt][0] = -1e30f;
                if (c0 + 1 > rl0) accS[nt][1] = -1e30f;
                if (c0     > rl1) accS[nt][2] = -1e30f;
                if (c0 + 1 > rl1) accS[nt][3] = -1e30f;
            }
        }

        // ---- online softmax
        float mx0 = -1e30f, mx1 = -1e30f;
#pragma unroll
        for (int nt = 0; nt < 8; nt++) {
            mx0 = fmaxf(mx0, fmaxf(accS[nt][0], accS[nt][1]));
            mx1 = fmaxf(mx1, fmaxf(accS[nt][2], accS[nt][3]));
        }
        mx0 = fmaxf(mx0, __shfl_xor_sync(0xffffffffu, mx0, 1));
        mx0 = fmaxf(mx0, __shfl_xor_sync(0xffffffffu, mx0, 2));
        mx1 = fmaxf(mx1, __shfl_xor_sync(0xffffffffu, mx1, 1));
        mx1 = fmaxf(mx1, __shfl_xor_sync(0xffffffffu, mx1, 2));
        const float mn0 = fmaxf(m0r, mx0);
        const float mn1 = fmaxf(m1r, mx1);
        const float cr0 = ex2(m0r - mn0);
        const float cr1 = ex2(m1r - mn1);
        m0r = mn0; m1r = mn1;

        float ps0 = 0.0f, ps1 = 0.0f;
#pragma unroll
        for (int nt = 0; nt < 8; nt++) {
            accS[nt][0] = ex2(accS[nt][0] - mn0);
            accS[nt][1] = ex2(accS[nt][1] - mn0);
            accS[nt][2] = ex2(accS[nt][2] - mn1);
            accS[nt][3] = ex2(accS[nt][3] - mn1);
            ps0 += accS[nt][0] + accS[nt][1];
            ps1 += accS[nt][2] + accS[nt][3];
        }
        ps0 += __shfl_xor_sync(0xffffffffu, ps0, 1);
        ps0 += __shfl_xor_sync(0xffffffffu, ps0, 2);
        ps1 += __shfl_xor_sync(0xffffffffu, ps1, 1);
        ps1 += __shfl_xor_sync(0xffffffffu, ps1, 2);
        l0 = l0 * cr0 + ps0;
        l1 = l1 * cr1 + ps1;
#pragma unroll
        for (int nt = 0; nt < 8; nt++) {
            accO[nt][0] *= cr0; accO[nt][1] *= cr0;
            accO[nt][2] *= cr1; accO[nt][3] *= cr1;
        }

        // ---- wait V(kt), then P store + PV
        if (kt + 4 <= qt) CP_WAIT1(); else CP_WAIT0();
        GBAR(g + 1);

        __syncwarp();
#pragma unroll
        for (int nt = 0; nt < 8; nt++) {
            const int c0 = nt * 8 + 2 * tg;
            const int sl = (c0 >> 4) * 16 + 4 * tg + 2 * (nt & 1);
            *(__half2*)&Ps[rl0 * 80 + sl] = __floats2half2_rn(accS[nt][0], accS[nt][1]);
            *(__half2*)&Ps[rl1 * 80 + sl] = __floats2half2_rn(accS[nt][2], accS[nt][3]);
        }
        __syncwarp();

        const __half* Vq = Vb + bi * KP;
#pragma unroll
        for (int gg = 0; gg < 4; gg++) {
            uint32_t af[4];
            uint2 lo = *(const uint2*)&Ps[rl0 * 80 + gg * 16 + tg * 4];
            uint2 hi = *(const uint2*)&Ps[rl1 * 80 + gg * 16 + tg * 4];
            af[0] = lo.x; af[1] = hi.x; af[2] = lo.y; af[3] = hi.y;
#pragma unroll
            for (int nt = 0; nt < 8; nt++) {
                uint2 bv = *(const uint2*)&Vq[(nt * 8 + gid) * 80 + gg * 16 + tg * 4];
                uint32_t bf[2] = {bv.x, bv.y};
                mma_f16(accO[nt], af, bf);
            }
        }

        if (kt + 4 <= qt) issueV(kt + 4, bi ^ 1);
        bi ^= 1;
    }

    // ---- 4-way merge of partial softmax states
    __syncthreads();                   // all groups done computing
    // groups 1..3 stash state in their own (now idle) K-buffer regions
    if (g > 0) {
        float* MB = (float*)(Sh + g * 5 * KP);
        float* OB = MB + 512;
        const int s = ltid;
        MB[s * 4 + 0] = m0r; MB[s * 4 + 1] = m1r;
        MB[s * 4 + 2] = l0;  MB[s * 4 + 3] = l1;
#pragma unroll
        for (int nt = 0; nt < 8; nt++)
#pragma unroll
            for (int v = 0; v < 4; v++)
                OB[s * 32 + nt * 4 + v] = accO[nt][v];
    }
    __syncthreads();
    if (g == 0) {
        const int s = ltid;
        float mm0 = m0r, mm1 = m1r;
#pragma unroll
        for (int gg = 1; gg < 4; gg++) {
            const float* MB = (const float*)(Sh + gg * 5 * KP);
            mm0 = fmaxf(mm0, MB[s * 4 + 0]);
            mm1 = fmaxf(mm1, MB[s * 4 + 1]);
        }
        const float ca0 = ex2(m0r - mm0);
        const float ca1 = ex2(m1r - mm1);
        float lt0 = l0 * ca0, lt1 = l1 * ca1;
        float oo[8][4];
#pragma unroll
        for (int nt = 0; nt < 8; nt++) {
            oo[nt][0] = accO[nt][0] * ca0;
            oo[nt][1] = accO[nt][1] * ca0;
            oo[nt][2] = accO[nt][2] * ca1;
            oo[nt][3] = accO[nt][3] * ca1;
        }
#pragma unroll
        for (int gg = 1; gg < 4; gg++) {
            const float* MB = (const float*)(Sh + gg * 5 * KP);
            const float* OB = MB + 512;
            const float cb0 = ex2(MB[s * 4 + 0] - mm0);
            const float cb1 = ex2(MB[s * 4 + 1] - mm1);
            lt0 += MB[s * 4 + 2] * cb0;
            lt1 += MB[s * 4 + 3] * cb1;
#pragma unroll
            for (int nt = 0; nt < 8; nt++) {
                oo[nt][0] += OB[s * 32 + nt * 4 + 0] * cb0;
                oo[nt][1] += OB[s * 32 + nt * 4 + 1] * cb0;
                oo[nt][2] += OB[s * 32 + nt * 4 + 2] * cb1;
                oo[nt][3] += OB[s * 32 + nt * 4 + 3] * cb1;
            }
        }
        const float inv0 = 1.0f / lt0;
        const float inv1 = 1.0f / lt1;
        const int gr0 = q0 + rl0;
        const int gr1 = q0 + rl1;
#pragma unroll
        for (int nt = 0; nt < 8; nt++) {
            const int c0 = nt * 8 + 2 * tg;
            const int sl = (c0 >> 4) * 16 + 4 * tg + 2 * (nt & 1);
            const int cb = h * 64 + sl;
            *(__half2*)&yp[(size_t)gr0 * C_DIM + cb] =
                __floats2half2_rn(oo[nt][0] * inv0, oo[nt][1] * inv0);
            *(__half2*)&yp[(size_t)gr1 * C_DIM + cb] =
                __floats2half2_rn(oo[nt][2] * inv1, oo[nt][3] * inv1);
        }
    }
}

// ---------------------------------------------------------------------------
extern "C" void kernel_launch(void* const* d_in, const int* in_sizes, int n_in,
                              void* d_out, int out_size)
{
    const float* x      = (const float*)d_in[0];
    const float* W_attn = (const float*)d_in[1];
    const float* b_attn = (const float*)d_in[2];
    const float* W_proj = (const float*)d_in[3];
    const float* b_proj = (const float*)d_in[4];
    float* out = (float*)d_out;

    __half *Qp, *Kp, *Vt, *y, *xp, *wa, *wp;
    cudaGetSymbolAddress((void**)&Qp, g_Qp);
    cudaGetSymbolAddress((void**)&Kp, g_Kp);
    cudaGetSymbolAddress((void**)&Vt, g_Vt);
    cudaGetSymbolAddress((void**)&y,  g_y);
    cudaGetSymbolAddress((void**)&xp, g_xp);
    cudaGetSymbolAddress((void**)&wa, g_wattn);
    cudaGetSymbolAddress((void**)&wp, g_wproj);

    const int smem_qkv  = 2 * (128 + 128) * 80 * 2;  // 81920
    const int smem_proj = 2 * (128 + 64) * 80 * 2;   // 61440
    cudaFuncSetAttribute(gemm_qkv, cudaFuncAttributeMaxDynamicSharedMemorySize, smem_qkv);
    cudaFuncSetAttribute(gemm_proj, cudaFuncAttributeMaxDynamicSharedMemorySize, smem_proj);
    cudaFuncSetAttribute(attn_kernel, cudaFuncAttributeMaxDynamicSharedMemorySize,
                         SM_ATTN_TOTAL);

    // 0) fused pre-pass (single launch)
    prep_all<<<PREP_XBLK + PREP_WA + PREP_WP, 256>>>(x, W_attn, W_proj, xp, wa, wp);

    // 1) qkv GEMM with scatter epilogue -> Qp/Kp/Vt
    {
        dim3 grid(C3 / 128, T_SEQ / 128);   // (18, 8) = 144
        gemm_qkv<<<grid, 256, smem_qkv>>>(xp, wa, b_attn, Qp, Kp, Vt);
    }
    // 2) attention (quad key-group) -> y (permuted fp16)
    {
        attn_kernel<<<(T_SEQ / 64) * NH, 512, SM_ATTN_TOTAL>>>(Qp, Kp, Vt, y);
    }
    // 3) proj GEMM -> out (fp32)
    {
        dim3 grid(C_DIM / 64, T_SEQ / 128); // (12, 8) = 96
        gemm_proj<<<grid, 256, smem_proj>>>(y, wp, b_proj, out);
    }
}